// round 1
// baseline (speedup 1.0000x reference)
#include <cuda_runtime.h>
#include <stdint.h>

#define NUM_CLASSES 10000
#define FEATURE_DIM 2048
#define BATCH 512
#define TPB 256
// ALPHA = 0.5 exactly -> powers of two via ldexpf

// Decoded labels (int), written by prep kernel each launch. Device scratch is
// allowed (no allocation APIs).
__device__ int g_lab[BATCH];

// ---------------------------------------------------------------------------
// Prep: (1) zero the loss scalar, (2) detect int64 vs int32 label encoding and
// decode labels into g_lab. One block of BATCH threads.
// int64 hypothesis holds iff for every sample the high 32-bit word is 0 and the
// low word is a valid class id. For genuine int32 data the "high words" are
// other random labels -> hypothesis rejected with overwhelming probability.
// ---------------------------------------------------------------------------
__global__ void prep_kernel(const int* __restrict__ labels_words,
                            float* __restrict__ loss_out) {
    __shared__ int s_not64;
    int tid = threadIdx.x;
    if (tid == 0) { s_not64 = 0; loss_out[0] = 0.0f; }
    __syncthreads();
    int lo = labels_words[2 * tid];
    int hi = labels_words[2 * tid + 1];
    if (hi != 0 || lo < 0 || lo >= NUM_CLASSES) s_not64 = 1;  // benign race
    __syncthreads();
    g_lab[tid] = s_not64 ? labels_words[tid] : lo;
}

// ---------------------------------------------------------------------------
// Main: one block per class row. Copy row; for matched batch samples apply the
// closed-form EMA  new_c = 2^-k * c + sum_r 2^-(k-r) * f_r  (batch order), and
// accumulate the (pre-update) MSE loss contribution.
// ---------------------------------------------------------------------------
__global__ void __launch_bounds__(TPB)
center_kernel(const float* __restrict__ features,
              const float* __restrict__ centers,
              float* __restrict__ out_centers,
              float* __restrict__ loss_out) {
    __shared__ int   s_match[BATCH];
    __shared__ float s_w[BATCH];
    __shared__ int   s_cnt;
    __shared__ float s_red[TPB / 32];

    const int l   = blockIdx.x;
    const int tid = threadIdx.x;

    if (tid == 0) s_cnt = 0;
    __syncthreads();

    // Parallel match scan over the 512 decoded labels (L1-resident).
    #pragma unroll
    for (int j = tid; j < BATCH; j += TPB) {
        if (g_lab[j] == l) {
            int p = atomicAdd(&s_cnt, 1);
            s_match[p] = j;
        }
    }
    __syncthreads();
    const int k = s_cnt;

    const float* crow = centers     + (size_t)l * FEATURE_DIM;
    float*       orow = out_centers + (size_t)l * FEATURE_DIM;

    if (k == 0) {
        // Pure row copy: the common case (>=9500 of 10000 rows).
        #pragma unroll
        for (int s = 0; s < FEATURE_DIM / TPB; s++) {
            int c = tid + s * TPB;
            orow[c] = __ldg(crow + c);
        }
        return;
    }

    // Restore batch order (atomic collection is unordered) + precompute weights.
    if (tid == 0) {
        for (int a = 1; a < k; a++) {
            int v = s_match[a];
            int b = a - 1;
            while (b >= 0 && s_match[b] > v) { s_match[b + 1] = s_match[b]; b--; }
            s_match[b + 1] = v;
        }
        for (int r = 0; r < k; r++) s_w[r] = ldexpf(1.0f, -(k - r));
    }
    __syncthreads();

    const float decay = ldexpf(1.0f, -k);
    float acc = 0.0f;

    #pragma unroll
    for (int s = 0; s < FEATURE_DIM / TPB; s++) {
        int c = tid + s * TPB;
        float cv = __ldg(crow + c);
        float nv = cv * decay;
        for (int r = 0; r < k; r++) {
            float f = __ldg(features + (size_t)s_match[r] * FEATURE_DIM + c);
            nv = fmaf(s_w[r], f, nv);
            float d = f - cv;            // loss uses ORIGINAL center row
            acc = fmaf(d, d, acc);
        }
        orow[c] = nv;
    }

    // Block-reduce loss partial, one atomicAdd per matched row (<=512 total).
    #pragma unroll
    for (int o = 16; o; o >>= 1) acc += __shfl_xor_sync(0xffffffffu, acc, o);
    if ((tid & 31) == 0) s_red[tid >> 5] = acc;
    __syncthreads();
    if (tid < TPB / 32) {
        acc = s_red[tid];
        #pragma unroll
        for (int o = (TPB / 64); o; o >>= 1)
            acc += __shfl_xor_sync((1u << (TPB / 32)) - 1u, acc, o);
        if (tid == 0)
            atomicAdd(loss_out, acc * (1.0f / ((float)BATCH * (float)FEATURE_DIM)));
    }
}

extern "C" void kernel_launch(void* const* d_in, const int* in_sizes, int n_in,
                              void* d_out, int out_size) {
    const float* features = (const float*)d_in[0];
    const int*   labels_w = (const int*)d_in[1];   // raw 32-bit words; decoded in prep
    const float* centers  = (const float*)d_in[2];

    float* out = (float*)d_out;
    // Loss scalar at [0]; centers block occupies the tail (robust to padding).
    float* out_centers = out + ((size_t)out_size - (size_t)NUM_CLASSES * FEATURE_DIM);

    prep_kernel<<<1, BATCH>>>(labels_w, out);
    center_kernel<<<NUM_CLASSES, TPB>>>(features, centers, out_centers, out);
}